// round 1
// baseline (speedup 1.0000x reference)
#include <cuda_runtime.h>
#include <math.h>
#include <float.h>
#include <stdint.h>

// ---------------- problem constants ----------------
#define CB    2
#define CS    2048
#define CHID  1024
#define CH    16
#define CKVH  8
#define CHD   64
#define CQN   (CH * CHD)      // 1024
#define CKN   (CKVH * CHD)    // 512
#define CSCALE 0.125f
#define CNEG  (-1000000000.0f)
#define KTH_IDX 715           // int((S-KEEP)*RATIO) - 1 = 716 - 1

// ---------------- scratch (static device globals; no allocs allowed) ----------------
__device__ float g_q[CB * CS * CQN];     // (b,s,h*64+d) after proj+rope
__device__ float g_k[CB * CS * CKN];     // (b,s,kvh*64+d)
__device__ float g_v[CB * CS * CKN];
__device__ float g_dyn[CB * CH * CS];    // (b,h,s): dyn, then thresholded bias in-place
__device__ int   g_fu[CB * CH];          // first unmasked key index per (b,h)
__device__ float g_attn[CB * CS * CQN];  // attention output, (b,s,h*64+d)

// ---------------- SGEMM: C[M,N] = A[M,K] @ W[N,K]^T (all row-major, f32) ----------------
// BM=BN=128, BK=16, 256 threads, 8x8 microtile.
__global__ void __launch_bounds__(256) sgemm_nt(const float* __restrict__ A,
                                                const float* __restrict__ W,
                                                float* __restrict__ C,
                                                int M, int N, int K) {
    __shared__ float As[16][128];
    __shared__ float Bs[16][128];

    const int tid = threadIdx.x;
    const int tx = tid & 15;
    const int ty = tid >> 4;
    const int m0 = blockIdx.y * 128;
    const int n0 = blockIdx.x * 128;

    const int lr = tid >> 1;          // 0..127
    const int lk = (tid & 1) * 8;     // 0 or 8

    const float* Aptr = A + (size_t)(m0 + lr) * K + lk;
    const float* Wptr = W + (size_t)(n0 + lr) * K + lk;

    float acc[8][8];
#pragma unroll
    for (int i = 0; i < 8; ++i)
#pragma unroll
        for (int j = 0; j < 8; ++j) acc[i][j] = 0.f;

    for (int k0 = 0; k0 < K; k0 += 16) {
        float4 a0 = *(const float4*)(Aptr + k0);
        float4 a1 = *(const float4*)(Aptr + k0 + 4);
        float4 b0 = *(const float4*)(Wptr + k0);
        float4 b1 = *(const float4*)(Wptr + k0 + 4);
        As[lk + 0][lr] = a0.x; As[lk + 1][lr] = a0.y; As[lk + 2][lr] = a0.z; As[lk + 3][lr] = a0.w;
        As[lk + 4][lr] = a1.x; As[lk + 5][lr] = a1.y; As[lk + 6][lr] = a1.z; As[lk + 7][lr] = a1.w;
        Bs[lk + 0][lr] = b0.x; Bs[lk + 1][lr] = b0.y; Bs[lk + 2][lr] = b0.z; Bs[lk + 3][lr] = b0.w;
        Bs[lk + 4][lr] = b1.x; Bs[lk + 5][lr] = b1.y; Bs[lk + 6][lr] = b1.z; Bs[lk + 7][lr] = b1.w;
        __syncthreads();

#pragma unroll
        for (int kk = 0; kk < 16; ++kk) {
            float4 x0 = *(const float4*)&As[kk][ty * 8];
            float4 x1 = *(const float4*)&As[kk][ty * 8 + 4];
            float4 y0 = *(const float4*)&Bs[kk][tx * 8];
            float4 y1 = *(const float4*)&Bs[kk][tx * 8 + 4];
            float xa[8] = {x0.x, x0.y, x0.z, x0.w, x1.x, x1.y, x1.z, x1.w};
            float ya[8] = {y0.x, y0.y, y0.z, y0.w, y1.x, y1.y, y1.z, y1.w};
#pragma unroll
            for (int i = 0; i < 8; ++i)
#pragma unroll
                for (int j = 0; j < 8; ++j) acc[i][j] = fmaf(xa[i], ya[j], acc[i][j]);
        }
        __syncthreads();
    }

#pragma unroll
    for (int i = 0; i < 8; ++i) {
        float* crow = C + (size_t)(m0 + ty * 8 + i) * N + n0 + tx * 8;
#pragma unroll
        for (int j = 0; j < 8; ++j) crow[j] = acc[i][j];
    }
}

// ---------------- RoPE on q (16 heads) and k (8 heads), in place ----------------
__global__ void rope_kernel(const float* __restrict__ cosp,
                            const float* __restrict__ sinp) {
    int idx = blockIdx.x * blockDim.x + threadIdx.x;  // < B*S*24*32
    int d  = idx & 31;
    int t  = idx >> 5;
    int hh = t % 24;
    int t2 = t / 24;
    int s  = t2 % CS;
    int b  = t2 / CS;

    const float* cb = cosp + ((size_t)b * CS + s) * CHD;
    const float* sb = sinp + ((size_t)b * CS + s) * CHD;
    float c1 = cb[d],      s1 = sb[d];
    float c2 = cb[d + 32], s2 = sb[d + 32];

    float* base;
    if (hh < CH) base = g_q + ((size_t)b * CS + s) * CQN + hh * CHD;
    else         base = g_k + ((size_t)b * CS + s) * CKN + (hh - CH) * CHD;

    float x1 = base[d];
    float x2 = base[d + 32];
    base[d]      = x1 * c1 - x2 * s1;   // x*cos + (-x_hi)*sin
    base[d + 32] = x2 * c2 + x1 * s2;   // x*cos + ( x_lo)*sin
}

// ---------------- dt -> dyn = exp(A[h] * softplus(dt)) ----------------
// one block per (b,s); dt[b,s,h] = v_row(512) . Wdt[h,:]
__global__ void __launch_bounds__(256) dt_kernel(const float* __restrict__ Wdt,
                                                 const float* __restrict__ Avec) {
    __shared__ float vsh[CKN];
    int bs = blockIdx.x;               // b*S + s
    int b = bs / CS, s = bs % CS;
    int tid = threadIdx.x;
    vsh[tid]        = g_v[(size_t)bs * CKN + tid];
    vsh[tid + 256]  = g_v[(size_t)bs * CKN + tid + 256];
    __syncthreads();

    int warp = tid >> 5, lane = tid & 31;
    for (int h = warp; h < CH; h += 8) {
        const float* wrow = Wdt + (size_t)h * CKN;
        float acc = 0.f;
        for (int j = lane; j < CKN; j += 32) acc = fmaf(vsh[j], wrow[j], acc);
#pragma unroll
        for (int off = 16; off > 0; off >>= 1)
            acc += __shfl_down_sync(0xffffffffu, acc, off);
        if (lane == 0) {
            float x = acc;
            float sp = fmaxf(x, 0.f) + log1pf(expf(-fabsf(x)));   // softplus
            g_dyn[((size_t)b * CH + h) * CS + s] = expf(Avec[h] * sp);
        }
    }
}

// ---------------- per-(b,h): sort 2048 dyn values, threshold, first-unmasked ----------------
__global__ void __launch_bounds__(256) rate_kernel() {
    __shared__ float sv[CS];
    __shared__ float s_rate;
    __shared__ int   s_fu;
    int bh = blockIdx.x;
    int tid = threadIdx.x;
    float* dptr = g_dyn + (size_t)bh * CS;

    for (int i = tid; i < CS; i += 256) sv[i] = dptr[i];
    __syncthreads();

    // bitonic sort ascending
    for (int k = 2; k <= CS; k <<= 1) {
        for (int j = k >> 1; j > 0; j >>= 1) {
            for (int i = tid; i < CS; i += 256) {
                int ixj = i ^ j;
                if (ixj > i) {
                    float a = sv[i], c = sv[ixj];
                    bool up = ((i & k) == 0);
                    if (up ? (a > c) : (a < c)) { sv[i] = c; sv[ixj] = a; }
                }
            }
            __syncthreads();
        }
    }
    if (tid == 0) { s_rate = sv[KTH_IDX]; s_fu = CS; }
    __syncthreads();

    float rate = s_rate;
    for (int i = tid; i < CS; i += 256) {
        float m = dptr[i];
        if (m < rate) dptr[i] = -FLT_MAX;
        else          atomicMin(&s_fu, i);
    }
    __syncthreads();
    if (tid == 0) g_fu[bh] = s_fu;
}

// ---------------- causal flash attention (64x64 tiles, f32 SIMT) ----------------
struct alignas(16) AttnSmem {
    float Qs[64][68];   // [d][qrow]
    float Ks[64][68];   // [d][krow]
    float Ps[64][68];   // [krow][qrow] (scores, then probabilities)
    float Vs[64][64];   // [krow][d]
    float mb[64];
    float m[64];
    float l[64];
    float scale[64];
    float red[4][64];
};

__global__ void __launch_bounds__(256) attn_kernel() {
    extern __shared__ char sm_raw[];
    AttnSmem& sm = *reinterpret_cast<AttnSmem*>(sm_raw);

    const int tid = threadIdx.x;
    const int qt = blockIdx.x;            // query tile
    const int bh = blockIdx.y;            // b*H + h
    const int b = bh >> 4, h = bh & 15;
    const int kvh = h >> 1;               // g = 2
    const int tx = tid & 15, ty = tid >> 4;

    const float* qbase = g_q + ((size_t)(b * CS + qt * 64)) * CQN + h * CHD;
    for (int idx = tid; idx < 4096; idx += 256) {
        int r = idx >> 6, d = idx & 63;
        sm.Qs[d][r] = qbase[(size_t)r * CQN + d];
    }
    if (tid < 64) { sm.m[tid] = -FLT_MAX; sm.l[tid] = 0.f; }
    float acc_o[4][4];
#pragma unroll
    for (int i = 0; i < 4; ++i)
#pragma unroll
        for (int j = 0; j < 4; ++j) acc_o[i][j] = 0.f;
    __syncthreads();

    const int rr = tid & 63, qrt = tid >> 6;

    for (int kt = 0; kt <= qt; ++kt) {
        const float* kbase = g_k + ((size_t)(b * CS + kt * 64)) * CKN + kvh * CHD;
        const float* vbase = g_v + ((size_t)(b * CS + kt * 64)) * CKN + kvh * CHD;
        for (int idx = tid; idx < 4096; idx += 256) {
            int r = idx >> 6, d = idx & 63;
            sm.Ks[d][r] = kbase[(size_t)r * CKN + d];
            sm.Vs[r][d] = vbase[(size_t)r * CKN + d];
        }
        if (tid < 64) sm.mb[tid] = g_dyn[(size_t)bh * CS + kt * 64 + tid];
        __syncthreads();

        // --- scores: Q_tile @ K_tile^T ---
        float acc[4][4];
#pragma unroll
        for (int i = 0; i < 4; ++i)
#pragma unroll
            for (int j = 0; j < 4; ++j) acc[i][j] = 0.f;

#pragma unroll 16
        for (int d = 0; d < 64; ++d) {
            float4 qa = *(const float4*)&sm.Qs[d][ty * 4];
            float4 kb = *(const float4*)&sm.Ks[d][tx * 4];
            float xa[4] = {qa.x, qa.y, qa.z, qa.w};
            float ya[4] = {kb.x, kb.y, kb.z, kb.w};
#pragma unroll
            for (int i = 0; i < 4; ++i)
#pragma unroll
                for (int j = 0; j < 4; ++j) acc[i][j] = fmaf(xa[i], ya[j], acc[i][j]);
        }

#pragma unroll
        for (int i = 0; i < 4; ++i) {
            int r = ty * 4 + i, qi = qt * 64 + r;
#pragma unroll
            for (int j = 0; j < 4; ++j) {
                int c = tx * 4 + j, ki = kt * 64 + c;
                float s_ = (ki <= qi) ? (acc[i][j] * CSCALE + sm.mb[c]) : -FLT_MAX;
                sm.Ps[c][r] = s_;
            }
        }
        __syncthreads();

        // --- row max (4 threads per row) ---
        float mx = -FLT_MAX;
#pragma unroll
        for (int c = 0; c < 16; ++c) mx = fmaxf(mx, sm.Ps[qrt * 16 + c][rr]);
        sm.red[qrt][rr] = mx;
        __syncthreads();
        if (tid < 64) {
            float mt = fmaxf(fmaxf(sm.red[0][tid], sm.red[1][tid]),
                             fmaxf(sm.red[2][tid], sm.red[3][tid]));
            float mnew = fmaxf(sm.m[tid], mt);
            sm.scale[tid] = expf(sm.m[tid] - mnew);
            sm.m[tid] = mnew;
        }
        __syncthreads();

        // --- exponentiate + row sums ---
        float rowm = sm.m[rr];
        float ssum = 0.f;
#pragma unroll
        for (int c = 0; c < 16; ++c) {
            float p = expf(sm.Ps[qrt * 16 + c][rr] - rowm);
            sm.Ps[qrt * 16 + c][rr] = p;
            ssum += p;
        }
        sm.red[qrt][rr] = ssum;
        __syncthreads();
        if (tid < 64)
            sm.l[tid] = sm.l[tid] * sm.scale[tid] +
                        (sm.red[0][tid] + sm.red[1][tid] + sm.red[2][tid] + sm.red[3][tid]);

        // --- rescale accumulators + P @ V ---
#pragma unroll
        for (int i = 0; i < 4; ++i) {
            float sc = sm.scale[ty * 4 + i];
#pragma unroll
            for (int j = 0; j < 4; ++j) acc_o[i][j] *= sc;
        }
#pragma unroll 16
        for (int kk = 0; kk < 64; ++kk) {
            float4 pa = *(const float4*)&sm.Ps[kk][ty * 4];
            float4 vb = *(const float4*)&sm.Vs[kk][tx * 4];
            float xa[4] = {pa.x, pa.y, pa.z, pa.w};
            float ya[4] = {vb.x, vb.y, vb.z, vb.w};
#pragma unroll
            for (int i = 0; i < 4; ++i)
#pragma unroll
                for (int j = 0; j < 4; ++j) acc_o[i][j] = fmaf(xa[i], ya[j], acc_o[i][j]);
        }
        __syncthreads();
    }

    float* obase = g_attn + ((size_t)(b * CS + qt * 64)) * CQN + h * CHD;
#pragma unroll
    for (int i = 0; i < 4; ++i) {
        int r = ty * 4 + i;
        float inv = 1.f / sm.l[r];
#pragma unroll
        for (int j = 0; j < 4; ++j)
            obase[(size_t)r * CQN + tx * 4 + j] = acc_o[i][j] * inv;
    }
}

// ---------------- exact full-row fixup for rows with fully-masked causal prefix ----------------
__global__ void __launch_bounds__(256) fixup_kernel() {
    __shared__ float qrow[CHD];
    __shared__ float s_sh[CS];
    __shared__ float red[256];
    __shared__ float s_max, s_den;

    int bh = blockIdx.x;
    int b = bh >> 4, h = bh & 15, kvh = h >> 1;
    int tid = threadIdx.x;
    int fu = g_fu[bh];
    if (fu <= 0) return;

    for (int qi = 0; qi < fu; ++qi) {
        if (tid < CHD) qrow[tid] = g_q[((size_t)(b * CS + qi)) * CQN + h * CHD + tid];
        __syncthreads();

        // scores for all keys (exact reference formula in f32)
        float lm = -FLT_MAX;
        for (int ki = tid; ki < CS; ki += 256) {
            const float* krow = g_k + ((size_t)(b * CS + ki)) * CKN + kvh * CHD;
            float dot = 0.f;
#pragma unroll 16
            for (int d = 0; d < CHD; ++d) dot = fmaf(qrow[d], krow[d], dot);
            float mv = g_dyn[(size_t)bh * CS + ki] + ((ki <= qi) ? 0.0f : CNEG);
            float sc = dot * CSCALE + mv;
            s_sh[ki] = sc;
            lm = fmaxf(lm, sc);
        }
        red[tid] = lm;
        __syncthreads();
        for (int off = 128; off > 0; off >>= 1) {
            if (tid < off) red[tid] = fmaxf(red[tid], red[tid + off]);
            __syncthreads();
        }
        if (tid == 0) s_max = red[0];
        __syncthreads();

        float ls = 0.f;
        float rmax = s_max;
        for (int ki = tid; ki < CS; ki += 256) {
            float w = expf(s_sh[ki] - rmax);
            s_sh[ki] = w;
            ls += w;
        }
        red[tid] = ls;
        __syncthreads();
        for (int off = 128; off > 0; off >>= 1) {
            if (tid < off) red[tid] += red[tid + off];
            __syncthreads();
        }
        if (tid == 0) s_den = red[0];
        __syncthreads();

        // out[d] = sum_ki w * v / den
        int d = tid & 63, part = tid >> 6;
        float oacc = 0.f;
        for (int ki = part; ki < CS; ki += 4)
            oacc = fmaf(s_sh[ki], g_v[((size_t)(b * CS + ki)) * CKN + kvh * CHD + d], oacc);
        red[tid] = oacc;
        __syncthreads();
        if (tid < 64) {
            float tot = red[tid] + red[tid + 64] + red[tid + 128] + red[tid + 192];
            g_attn[((size_t)(b * CS + qi)) * CQN + h * CHD + d] = tot / s_den;
        }
        __syncthreads();
    }
}

// ---------------- host launcher ----------------
extern "C" void kernel_launch(void* const* d_in, const int* in_sizes, int n_in,
                              void* d_out, int out_size) {
    const float* hs   = (const float*)d_in[0];
    const float* cosp = (const float*)d_in[1];
    const float* sinp = (const float*)d_in[2];
    // d_in[3] attention_mask: deterministic causal, computed analytically
    const float* Wq   = (const float*)d_in[4];
    const float* Wk   = (const float*)d_in[5];
    const float* Wv   = (const float*)d_in[6];
    const float* Avec = (const float*)d_in[7];
    const float* Wdt  = (const float*)d_in[8];
    const float* Wo   = (const float*)d_in[9];
    float* out = (float*)d_out;

    float *pq, *pk, *pv, *pattn;
    cudaGetSymbolAddress((void**)&pq, g_q);
    cudaGetSymbolAddress((void**)&pk, g_k);
    cudaGetSymbolAddress((void**)&pv, g_v);
    cudaGetSymbolAddress((void**)&pattn, g_attn);

    const int M = CB * CS;  // 4096

    // projections
    sgemm_nt<<<dim3(CQN / 128, M / 128), 256>>>(hs, Wq, pq, M, CQN, CHID);
    sgemm_nt<<<dim3(CKN / 128, M / 128), 256>>>(hs, Wk, pk, M, CKN, CHID);
    sgemm_nt<<<dim3(CKN / 128, M / 128), 256>>>(hs, Wv, pv, M, CKN, CHID);

    // rope on q,k
    rope_kernel<<<(CB * CS * (CH + CKVH) * 32) / 256, 256>>>(cosp, sinp);

    // dyn mask pipeline
    dt_kernel<<<M, 256>>>(Wdt, Avec);
    rate_kernel<<<CB * CH, 256>>>();

    // attention
    int smem_bytes = (int)sizeof(AttnSmem);
    cudaFuncSetAttribute(attn_kernel, cudaFuncAttributeMaxDynamicSharedMemorySize, smem_bytes);
    attn_kernel<<<dim3(CS / 64, CB * CH), 256, smem_bytes>>>();
    fixup_kernel<<<CB * CH, 256>>>();

    // output projection
    sgemm_nt<<<dim3(CHID / 128, M / 128), 256>>>(pattn, Wo, out, M, CHID, CQN);
}

// round 3
// speedup vs baseline: 1.4085x; 1.4085x over previous
#include <cuda_runtime.h>
#include <cuda_bf16.h>
#include <math.h>
#include <float.h>
#include <stdint.h>

// ---------------- problem constants ----------------
#define CB    2
#define CS    2048
#define CHID  1024
#define CH    16
#define CKVH  8
#define CHD   64
#define CQN   (CH * CHD)      // 1024
#define CKN   (CKVH * CHD)    // 512
#define CSCALE 0.125f
#define CNEG  (-1000000000.0f)
#define KTH_IDX 715           // int((S-KEEP)*RATIO) - 1 = 716 - 1

// ---------------- scratch (static device globals; no allocs allowed) ----------------
__device__ float g_q[CB * CS * CQN];     // (b,s,h*64+d) after proj+rope
__device__ float g_k[CB * CS * CKN];     // (b,s,kvh*64+d)
__device__ float g_v[CB * CS * CKN];
__device__ float g_dyn[CB * CH * CS];    // (b,h,s): dyn, then thresholded bias in-place
__device__ int   g_fu[CB * CH];          // first unmasked key index per (b,h)
__device__ float g_attn[CB * CS * CQN];  // attention output, (b,s,h*64+d)

// ================= mma.sync helpers (baseline PTX ISA, valid on compute_103) =================
__device__ __forceinline__ uint32_t smem_u32(const void* p) {
    uint32_t a;
    asm("{ .reg .u64 t; cvta.to.shared.u64 t, %1; cvt.u32.u64 %0, t; }" : "=r"(a) : "l"(p));
    return a;
}
__device__ __forceinline__ void ldm_x4(uint32_t* r, uint32_t addr) {
    asm volatile("ldmatrix.sync.aligned.m8n8.x4.shared.b16 {%0,%1,%2,%3}, [%4];"
                 : "=r"(r[0]), "=r"(r[1]), "=r"(r[2]), "=r"(r[3]) : "r"(addr));
}
__device__ __forceinline__ void mma_bf16(float* c, const uint32_t* a, const uint32_t* b) {
    asm volatile(
        "mma.sync.aligned.m16n8k16.row.col.f32.bf16.bf16.f32 "
        "{%0,%1,%2,%3}, {%4,%5,%6,%7}, {%8,%9}, {%0,%1,%2,%3};"
        : "+f"(c[0]), "+f"(c[1]), "+f"(c[2]), "+f"(c[3])
        : "r"(a[0]), "r"(a[1]), "r"(a[2]), "r"(a[3]), "r"(b[0]), "r"(b[1]));
}

// pack two f32 -> bf16x2 (e0 low half, e1 high half)
__device__ __forceinline__ uint32_t bf2(float e0, float e1) {
    uint32_t r;
    asm("cvt.rn.bf16x2.f32 %0, %1, %2;" : "=r"(r) : "f"(e1), "f"(e0));
    return r;
}
__device__ __forceinline__ float hif_lo(uint32_t h) { return __uint_as_float(h << 16); }
__device__ __forceinline__ float hif_hi(uint32_t h) { return __uint_as_float(h & 0xFFFF0000u); }

// ============ mma.sync bf16x3 GEMM: C[M,N] = A[M,K] @ W[N,K]^T (f32 in/out) ============
// Tile 128x128, BK=32, 256 threads (8 warps, each 64x32).
// smem tiles padded to 40 halves (80B) per row -> conflict-free ldmatrix.
#define MG_TILE   10240                 // 128 rows * 80 B
#define MG_STAGE  (4 * MG_TILE)         // Ah, Al, Bh, Bl
#define MG_SMEM   (2 * MG_STAGE)        // double buffered (81920 B)

// convert 16 f32 (4x float4) into 16 hi-bf16 + 16 lo-bf16, store to smem
__device__ __forceinline__ void sts_split(char* hi, char* lo, const float4* v) {
    uint32_t h[8], l[8];
#pragma unroll
    for (int j = 0; j < 4; ++j) {
        uint32_t h0 = bf2(v[j].x, v[j].y);
        uint32_t h1 = bf2(v[j].z, v[j].w);
        h[2 * j] = h0; h[2 * j + 1] = h1;
        l[2 * j]     = bf2(v[j].x - hif_lo(h0), v[j].y - hif_hi(h0));
        l[2 * j + 1] = bf2(v[j].z - hif_lo(h1), v[j].w - hif_hi(h1));
    }
    *(uint4*)(hi)      = make_uint4(h[0], h[1], h[2], h[3]);
    *(uint4*)(hi + 16) = make_uint4(h[4], h[5], h[6], h[7]);
    *(uint4*)(lo)      = make_uint4(l[0], l[1], l[2], l[3]);
    *(uint4*)(lo + 16) = make_uint4(l[4], l[5], l[6], l[7]);
}

__global__ void __launch_bounds__(256) mgemm_nt(const float* __restrict__ A,
                                                const float* __restrict__ W,
                                                float* __restrict__ C,
                                                int M, int N, int K) {
    extern __shared__ char sm[];
    const uint32_t sbase = smem_u32(sm);

    const int tid = threadIdx.x;
    const int wid = tid >> 5, lane = tid & 31;
    const int m0 = blockIdx.y * 128, n0 = blockIdx.x * 128;
    const int wm = wid & 1, wn = wid >> 1;       // warp tile: rows wm*64, cols wn*32

    // loader mapping: each thread owns one (row, k-half) of the 128x32 chunk
    const int lrow = tid >> 1;
    const int lkh  = (tid & 1) * 16;
    const float* aptr = A + (size_t)(m0 + lrow) * K + lkh;
    const float* bptr = W + (size_t)(n0 + lrow) * K + lkh;
    const int stsoff = lrow * 80 + lkh * 2;

    float acc[4][4][4];
#pragma unroll
    for (int i = 0; i < 4; ++i)
#pragma unroll
        for (int j = 0; j < 4; ++j)
#pragma unroll
            for (int q = 0; q < 4; ++q) acc[i][j][q] = 0.f;

    const int nchunk = K >> 5;

    // prologue: stage chunk 0 into buffer 0
    {
        float4 av[4], bv[4];
#pragma unroll
        for (int j = 0; j < 4; ++j) { av[j] = *(const float4*)(aptr + j * 4); bv[j] = *(const float4*)(bptr + j * 4); }
        sts_split(sm + 0 * MG_TILE + stsoff, sm + 1 * MG_TILE + stsoff, av);
        sts_split(sm + 2 * MG_TILE + stsoff, sm + 3 * MG_TILE + stsoff, bv);
    }
    __syncthreads();

    for (int c = 0; c < nchunk; ++c) {
        const int p = c & 1;
        const uint32_t buf = sbase + p * MG_STAGE;

        // prefetch next chunk to registers (overlaps with MMA below)
        float4 av[4], bv[4];
        if (c + 1 < nchunk) {
            const float* ap = aptr + (c + 1) * 32;
            const float* bp = bptr + (c + 1) * 32;
#pragma unroll
            for (int j = 0; j < 4; ++j) { av[j] = *(const float4*)(ap + j * 4); bv[j] = *(const float4*)(bp + j * 4); }
        }

        // ---- MMA phase on buffer p ----
#pragma unroll
        for (int ks = 0; ks < 2; ++ks) {
            const int kk = ks * 16;
            // B fragments: 4 n-frags of (n8,k16), hi and lo
            uint32_t bh[4][2], bl[4][2];
#pragma unroll
            for (int half = 0; half < 2; ++half) {
                const int n = wn * 32 + half * 16;
                const uint32_t rowb = (uint32_t)(n + (lane & 7) + ((lane & 16) >> 1));
                const uint32_t colb = (uint32_t)(kk + (lane & 8));
                const uint32_t addr = buf + 2 * MG_TILE + rowb * 80 + colb * 2;
                uint32_t r[4];
                ldm_x4(r, addr);
                bh[half * 2][0] = r[0]; bh[half * 2][1] = r[1];
                bh[half * 2 + 1][0] = r[2]; bh[half * 2 + 1][1] = r[3];
                ldm_x4(r, addr + MG_TILE);
                bl[half * 2][0] = r[0]; bl[half * 2][1] = r[1];
                bl[half * 2 + 1][0] = r[2]; bl[half * 2 + 1][1] = r[3];
            }
#pragma unroll
            for (int mf = 0; mf < 4; ++mf) {
                const int m = wm * 64 + mf * 16;
                const uint32_t rowa = (uint32_t)(m + (lane & 15));
                const uint32_t cola = (uint32_t)(kk + ((lane >> 4) << 3));
                const uint32_t addr = buf + rowa * 80 + cola * 2;
                uint32_t ah[4], al[4];
                ldm_x4(ah, addr);
                ldm_x4(al, addr + MG_TILE);
#pragma unroll
                for (int nf = 0; nf < 4; ++nf) {
                    mma_bf16(acc[mf][nf], ah, bh[nf]);   // Ah*Bh
                    mma_bf16(acc[mf][nf], ah, bl[nf]);   // Ah*Bl
                    mma_bf16(acc[mf][nf], al, bh[nf]);   // Al*Bh
                }
            }
        }

        // ---- stage next chunk into buffer p^1 ----
        if (c + 1 < nchunk) {
            char* nb = sm + (p ^ 1) * MG_STAGE;
            sts_split(nb + 0 * MG_TILE + stsoff, nb + 1 * MG_TILE + stsoff, av);
            sts_split(nb + 2 * MG_TILE + stsoff, nb + 3 * MG_TILE + stsoff, bv);
            __syncthreads();
        }
    }

    // ---- epilogue: c-frag lane layout: c0,c1 = C[m + lane/4][n + (lane%4)*2 (+1)]; c2,c3 same m+8
#pragma unroll
    for (int mf = 0; mf < 4; ++mf) {
        const int row = m0 + wm * 64 + mf * 16 + (lane >> 2);
#pragma unroll
        for (int nf = 0; nf < 4; ++nf) {
            const int col = n0 + wn * 32 + nf * 8 + (lane & 3) * 2;
            *(float2*)(C + (size_t)row * N + col)       = make_float2(acc[mf][nf][0], acc[mf][nf][1]);
            *(float2*)(C + (size_t)(row + 8) * N + col) = make_float2(acc[mf][nf][2], acc[mf][nf][3]);
        }
    }
}

// ---------------- RoPE on q (16 heads) and k (8 heads), in place ----------------
__global__ void rope_kernel(const float* __restrict__ cosp,
                            const float* __restrict__ sinp) {
    int idx = blockIdx.x * blockDim.x + threadIdx.x;  // < B*S*24*32
    int d  = idx & 31;
    int t  = idx >> 5;
    int hh = t % 24;
    int t2 = t / 24;
    int s  = t2 % CS;
    int b  = t2 / CS;

    const float* cb = cosp + ((size_t)b * CS + s) * CHD;
    const float* sb = sinp + ((size_t)b * CS + s) * CHD;
    float c1 = cb[d],      s1 = sb[d];
    float c2 = cb[d + 32], s2 = sb[d + 32];

    float* base;
    if (hh < CH) base = g_q + ((size_t)b * CS + s) * CQN + hh * CHD;
    else         base = g_k + ((size_t)b * CS + s) * CKN + (hh - CH) * CHD;

    float x1 = base[d];
    float x2 = base[d + 32];
    base[d]      = x1 * c1 - x2 * s1;
    base[d + 32] = x2 * c2 + x1 * s2;
}

// ---------------- dt -> dyn = exp(A[h] * softplus(dt)) ----------------
__global__ void __launch_bounds__(256) dt_kernel(const float* __restrict__ Wdt,
                                                 const float* __restrict__ Avec) {
    __shared__ float vsh[CKN];
    int bs = blockIdx.x;               // b*S + s
    int b = bs / CS, s = bs % CS;
    int tid = threadIdx.x;
    vsh[tid]        = g_v[(size_t)bs * CKN + tid];
    vsh[tid + 256]  = g_v[(size_t)bs * CKN + tid + 256];
    __syncthreads();

    int warp = tid >> 5, lane = tid & 31;
    for (int h = warp; h < CH; h += 8) {
        const float* wrow = Wdt + (size_t)h * CKN;
        float acc = 0.f;
        for (int j = lane; j < CKN; j += 32) acc = fmaf(vsh[j], wrow[j], acc);
#pragma unroll
        for (int off = 16; off > 0; off >>= 1)
            acc += __shfl_down_sync(0xffffffffu, acc, off);
        if (lane == 0) {
            float x = acc;
            float sp = fmaxf(x, 0.f) + log1pf(expf(-fabsf(x)));   // softplus
            g_dyn[((size_t)b * CH + h) * CS + s] = expf(Avec[h] * sp);
        }
    }
}

// ---------------- per-(b,h): sort 2048 dyn values, threshold, first-unmasked ----------------
__global__ void __launch_bounds__(256) rate_kernel() {
    __shared__ float sv[CS];
    __shared__ float s_rate;
    __shared__ int   s_fu;
    int bh = blockIdx.x;
    int tid = threadIdx.x;
    float* dptr = g_dyn + (size_t)bh * CS;

    for (int i = tid; i < CS; i += 256) sv[i] = dptr[i];
    __syncthreads();

    for (int k = 2; k <= CS; k <<= 1) {
        for (int j = k >> 1; j > 0; j >>= 1) {
            for (int i = tid; i < CS; i += 256) {
                int ixj = i ^ j;
                if (ixj > i) {
                    float a = sv[i], c = sv[ixj];
                    bool up = ((i & k) == 0);
                    if (up ? (a > c) : (a < c)) { sv[i] = c; sv[ixj] = a; }
                }
            }
            __syncthreads();
        }
    }
    if (tid == 0) { s_rate = sv[KTH_IDX]; s_fu = CS; }
    __syncthreads();

    float rate = s_rate;
    for (int i = tid; i < CS; i += 256) {
        float m = dptr[i];
        if (m < rate) dptr[i] = -FLT_MAX;
        else          atomicMin(&s_fu, i);
    }
    __syncthreads();
    if (tid == 0) g_fu[bh] = s_fu;
}

// ---------------- causal flash attention (64x64 tiles, f32 SIMT) ----------------
struct alignas(16) AttnSmem {
    float Qs[64][68];   // [d][qrow]
    float Ks[64][68];   // [d][krow]
    float Ps[64][68];   // [krow][qrow]
    float Vs[64][64];   // [krow][d]
    float mb[64];
    float m[64];
    float l[64];
    float scale[64];
    float red[4][64];
};

__global__ void __launch_bounds__(256) attn_kernel() {
    extern __shared__ char sm_raw[];
    AttnSmem& sm = *reinterpret_cast<AttnSmem*>(sm_raw);

    const int tid = threadIdx.x;
    const int qt = blockIdx.x;
    const int bh = blockIdx.y;
    const int b = bh >> 4, h = bh & 15;
    const int kvh = h >> 1;
    const int tx = tid & 15, ty = tid >> 4;

    const float* qbase = g_q + ((size_t)(b * CS + qt * 64)) * CQN + h * CHD;
    for (int idx = tid; idx < 4096; idx += 256) {
        int r = idx >> 6, d = idx & 63;
        sm.Qs[d][r] = qbase[(size_t)r * CQN + d];
    }
    if (tid < 64) { sm.m[tid] = -FLT_MAX; sm.l[tid] = 0.f; }
    float acc_o[4][4];
#pragma unroll
    for (int i = 0; i < 4; ++i)
#pragma unroll
        for (int j = 0; j < 4; ++j) acc_o[i][j] = 0.f;
    __syncthreads();

    const int rr = tid & 63, qrt = tid >> 6;

    for (int kt = 0; kt <= qt; ++kt) {
        const float* kbase = g_k + ((size_t)(b * CS + kt * 64)) * CKN + kvh * CHD;
        const float* vbase = g_v + ((size_t)(b * CS + kt * 64)) * CKN + kvh * CHD;
        for (int idx = tid; idx < 4096; idx += 256) {
            int r = idx >> 6, d = idx & 63;
            sm.Ks[d][r] = kbase[(size_t)r * CKN + d];
            sm.Vs[r][d] = vbase[(size_t)r * CKN + d];
        }
        if (tid < 64) sm.mb[tid] = g_dyn[(size_t)bh * CS + kt * 64 + tid];
        __syncthreads();

        float acc[4][4];
#pragma unroll
        for (int i = 0; i < 4; ++i)
#pragma unroll
            for (int j = 0; j < 4; ++j) acc[i][j] = 0.f;

#pragma unroll 16
        for (int d = 0; d < 64; ++d) {
            float4 qa = *(const float4*)&sm.Qs[d][ty * 4];
            float4 kb = *(const float4*)&sm.Ks[d][tx * 4];
            float xa[4] = {qa.x, qa.y, qa.z, qa.w};
            float ya[4] = {kb.x, kb.y, kb.z, kb.w};
#pragma unroll
            for (int i = 0; i < 4; ++i)
#pragma unroll
                for (int j = 0; j < 4; ++j) acc[i][j] = fmaf(xa[i], ya[j], acc[i][j]);
        }

#pragma unroll
        for (int i = 0; i < 4; ++i) {
            int r = ty * 4 + i, qi = qt * 64 + r;
#pragma unroll
            for (int j = 0; j < 4; ++j) {
                int c = tx * 4 + j, ki = kt * 64 + c;
                float s_ = (ki <= qi) ? (acc[i][j] * CSCALE + sm.mb[c]) : -FLT_MAX;
                sm.Ps[c][r] = s_;
            }
        }
        __syncthreads();

        float mx = -FLT_MAX;
#pragma unroll
        for (int c = 0; c < 16; ++c) mx = fmaxf(mx, sm.Ps[qrt * 16 + c][rr]);
        sm.red[qrt][rr] = mx;
        __syncthreads();
        if (tid < 64) {
            float mt = fmaxf(fmaxf(sm.red[0][tid], sm.red[1][tid]),
                             fmaxf(sm.red[2][tid], sm.red[3][tid]));
            float mnew = fmaxf(sm.m[tid], mt);
            sm.scale[tid] = expf(sm.m[tid] - mnew);
            sm.m[tid] = mnew;
        }
        __syncthreads();

        float rowm = sm.m[rr];
        float ssum = 0.f;
#pragma unroll
        for (int c = 0; c < 16; ++c) {
            float p = expf(sm.Ps[qrt * 16 + c][rr] - rowm);
            sm.Ps[qrt * 16 + c][rr] = p;
            ssum += p;
        }
        sm.red[qrt][rr] = ssum;
        __syncthreads();
        if (tid < 64)
            sm.l[tid] = sm.l[tid] * sm.scale[tid] +
                        (sm.red[0][tid] + sm.red[1][tid] + sm.red[2][tid] + sm.red[3][tid]);

#pragma unroll
        for (int i = 0; i < 4; ++i) {
            float sc = sm.scale[ty * 4 + i];
#pragma unroll
            for (int j = 0; j < 4; ++j) acc_o[i][j] *= sc;
        }
#pragma unroll 16
        for (int kk = 0; kk < 64; ++kk) {
            float4 pa = *(const float4*)&sm.Ps[kk][ty * 4];
            float4 vb = *(const float4*)&sm.Vs[kk][tx * 4];
            float xa[4] = {pa.x, pa.y, pa.z, pa.w};
            float ya[4] = {vb.x, vb.y, vb.z, vb.w};
#pragma unroll
            for (int i = 0; i < 4; ++i)
#pragma unroll
                for (int j = 0; j < 4; ++j) acc_o[i][j] = fmaf(xa[i], ya[j], acc_o[i][j]);
        }
        __syncthreads();
    }

    float* obase = g_attn + ((size_t)(b * CS + qt * 64)) * CQN + h * CHD;
#pragma unroll
    for (int i = 0; i < 4; ++i) {
        int r = ty * 4 + i;
        float inv = 1.f / sm.l[r];
#pragma unroll
        for (int j = 0; j < 4; ++j)
            obase[(size_t)r * CQN + tx * 4 + j] = acc_o[i][j] * inv;
    }
}

// ---------------- exact full-row fixup for rows with fully-masked causal prefix ----------------
__global__ void __launch_bounds__(256) fixup_kernel() {
    __shared__ float qrow[CHD];
    __shared__ float s_sh[CS];
    __shared__ float red[256];
    __shared__ float s_max, s_den;

    int bh = blockIdx.x;
    int b = bh >> 4, h = bh & 15, kvh = h >> 1;
    int tid = threadIdx.x;
    int fu = g_fu[bh];
    if (fu <= 0) return;

    for (int qi = 0; qi < fu; ++qi) {
        if (tid < CHD) qrow[tid] = g_q[((size_t)(b * CS + qi)) * CQN + h * CHD + tid];
        __syncthreads();

        float lm = -FLT_MAX;
        for (int ki = tid; ki < CS; ki += 256) {
            const float* krow = g_k + ((size_t)(b * CS + ki)) * CKN + kvh * CHD;
            float dot = 0.f;
#pragma unroll 16
            for (int d = 0; d < CHD; ++d) dot = fmaf(qrow[d], krow[d], dot);
            float mv = g_dyn[(size_t)bh * CS + ki] + ((ki <= qi) ? 0.0f : CNEG);
            float sc = dot * CSCALE + mv;
            s_sh[ki] = sc;
            lm = fmaxf(lm, sc);
        }
        red[tid] = lm;
        __syncthreads();
        for (int off = 128; off > 0; off >>= 1) {
            if (tid < off) red[tid] = fmaxf(red[tid], red[tid + off]);
            __syncthreads();
        }
        if (tid == 0) s_max = red[0];
        __syncthreads();

        float ls = 0.f;
        float rmax = s_max;
        for (int ki = tid; ki < CS; ki += 256) {
            float w = expf(s_sh[ki] - rmax);
            s_sh[ki] = w;
            ls += w;
        }
        red[tid] = ls;
        __syncthreads();
        for (int off = 128; off > 0; off >>= 1) {
            if (tid < off) red[tid] += red[tid + off];
            __syncthreads();
        }
        if (tid == 0) s_den = red[0];
        __syncthreads();

        int d = tid & 63, part = tid >> 6;
        float oacc = 0.f;
        for (int ki = part; ki < CS; ki += 4)
            oacc = fmaf(s_sh[ki], g_v[((size_t)(b * CS + ki)) * CKN + kvh * CHD + d], oacc);
        red[tid] = oacc;
        __syncthreads();
        if (tid < 64) {
            float tot = red[tid] + red[tid + 64] + red[tid + 128] + red[tid + 192];
            g_attn[((size_t)(b * CS + qi)) * CQN + h * CHD + d] = tot / s_den;
        }
        __syncthreads();
    }
}

// ---------------- host launcher ----------------
static void launch_mgemm(const float* A, const float* W, float* C, int M, int N, int K) {
    cudaFuncSetAttribute(mgemm_nt, cudaFuncAttributeMaxDynamicSharedMemorySize, MG_SMEM);
    mgemm_nt<<<dim3(N / 128, M / 128), 256, MG_SMEM>>>(A, W, C, M, N, K);
}

extern "C" void kernel_launch(void* const* d_in, const int* in_sizes, int n_in,
                              void* d_out, int out_size) {
    const float* hs   = (const float*)d_in[0];
    const float* cosp = (const float*)d_in[1];
    const float* sinp = (const float*)d_in[2];
    const float* Wq   = (const float*)d_in[4];
    const float* Wk   = (const float*)d_in[5];
    const float* Wv   = (const float*)d_in[6];
    const float* Avec = (const float*)d_in[7];
    const float* Wdt  = (const float*)d_in[8];
    const float* Wo   = (const float*)d_in[9];
    float* out = (float*)d_out;

    float *pq, *pk, *pv, *pattn;
    cudaGetSymbolAddress((void**)&pq, g_q);
    cudaGetSymbolAddress((void**)&pk, g_k);
    cudaGetSymbolAddress((void**)&pv, g_v);
    cudaGetSymbolAddress((void**)&pattn, g_attn);

    const int M = CB * CS;  // 4096

    // projections on HMMA (bf16x3 via mma.sync)
    launch_mgemm(hs, Wq, pq, M, CQN, CHID);
    launch_mgemm(hs, Wk, pk, M, CKN, CHID);
    launch_mgemm(hs, Wv, pv, M, CKN, CHID);

    // rope on q,k
    rope_kernel<<<(CB * CS * (CH + CKVH) * 32) / 256, 256>>>(cosp, sinp);

    // dyn mask pipeline
    dt_kernel<<<M, 256>>>(Wdt, Avec);
    rate_kernel<<<CB * CH, 256>>>();

    // attention
    int smem_bytes = (int)sizeof(AttnSmem);
    cudaFuncSetAttribute(attn_kernel, cudaFuncAttributeMaxDynamicSharedMemorySize, smem_bytes);
    attn_kernel<<<dim3(CS / 64, CB * CH), 256, smem_bytes>>>();
    fixup_kernel<<<CB * CH, 256>>>();

    // output projection
    launch_mgemm(pattn, Wo, out, M, CHID, CQN);
}

// round 4
// speedup vs baseline: 2.0762x; 1.4740x over previous
#include <cuda_runtime.h>
#include <cuda_bf16.h>
#include <math.h>
#include <float.h>
#include <stdint.h>

// ---------------- problem constants ----------------
#define CB    2
#define CS    2048
#define CHID  1024
#define CH    16
#define CKVH  8
#define CHD   64
#define CQN   (CH * CHD)      // 1024
#define CKN   (CKVH * CHD)    // 512
#define CSCALE 0.125f
#define CNEG  (-1000000000.0f)
#define KTH_IDX 715           // int((S-KEEP)*RATIO) - 1 = 716 - 1

// ---------------- scratch (static device globals; no allocs allowed) ----------------
__device__ float g_q[CB * CS * CQN];     // (b,s,h*64+d) after proj+rope
__device__ float g_k[CB * CS * CKN];     // (b,s,kvh*64+d)
__device__ float g_v[CB * CS * CKN];
__device__ float g_dyn[CB * CH * CS];    // (b,h,s): dyn, then thresholded bias in-place
__device__ int   g_fu[CB * CH];          // first unmasked key index per (b,h)
__device__ float g_attn[CB * CS * CQN];  // attention output, (b,s,h*64+d)

// ================= mma.sync helpers (baseline PTX ISA, valid on compute_103) =================
__device__ __forceinline__ uint32_t smem_u32(const void* p) {
    uint32_t a;
    asm("{ .reg .u64 t; cvta.to.shared.u64 t, %1; cvt.u32.u64 %0, t; }" : "=r"(a) : "l"(p));
    return a;
}
__device__ __forceinline__ void ldm_x4(uint32_t* r, uint32_t addr) {
    asm volatile("ldmatrix.sync.aligned.m8n8.x4.shared.b16 {%0,%1,%2,%3}, [%4];"
                 : "=r"(r[0]), "=r"(r[1]), "=r"(r[2]), "=r"(r[3]) : "r"(addr));
}
__device__ __forceinline__ void mma_bf16(float* c, const uint32_t* a, const uint32_t* b) {
    asm volatile(
        "mma.sync.aligned.m16n8k16.row.col.f32.bf16.bf16.f32 "
        "{%0,%1,%2,%3}, {%4,%5,%6,%7}, {%8,%9}, {%0,%1,%2,%3};"
        : "+f"(c[0]), "+f"(c[1]), "+f"(c[2]), "+f"(c[3])
        : "r"(a[0]), "r"(a[1]), "r"(a[2]), "r"(a[3]), "r"(b[0]), "r"(b[1]));
}

// pack two f32 -> bf16x2 (e0 low half, e1 high half)
__device__ __forceinline__ uint32_t bf2(float e0, float e1) {
    uint32_t r;
    asm("cvt.rn.bf16x2.f32 %0, %1, %2;" : "=r"(r) : "f"(e1), "f"(e0));
    return r;
}
__device__ __forceinline__ float hif_lo(uint32_t h) { return __uint_as_float(h << 16); }
__device__ __forceinline__ float hif_hi(uint32_t h) { return __uint_as_float(h & 0xFFFF0000u); }

// ============ mma.sync bf16x3 GEMM: C[M,N] = A[M,K] @ W[N,K]^T (f32 in/out) ============
// Tile 128x128, BK=32, 256 threads (8 warps, each 64x32).
// smem tiles padded to 40 halves (80B) per row -> conflict-free ldmatrix.
#define MG_TILE   10240                 // 128 rows * 80 B
#define MG_STAGE  (4 * MG_TILE)         // Ah, Al, Bh, Bl
#define MG_SMEM   (2 * MG_STAGE)        // double buffered (81920 B)

// convert 16 f32 (4x float4) into 16 hi-bf16 + 16 lo-bf16, store to smem
__device__ __forceinline__ void sts_split(char* hi, char* lo, const float4* v) {
    uint32_t h[8], l[8];
#pragma unroll
    for (int j = 0; j < 4; ++j) {
        uint32_t h0 = bf2(v[j].x, v[j].y);
        uint32_t h1 = bf2(v[j].z, v[j].w);
        h[2 * j] = h0; h[2 * j + 1] = h1;
        l[2 * j]     = bf2(v[j].x - hif_lo(h0), v[j].y - hif_hi(h0));
        l[2 * j + 1] = bf2(v[j].z - hif_lo(h1), v[j].w - hif_hi(h1));
    }
    *(uint4*)(hi)      = make_uint4(h[0], h[1], h[2], h[3]);
    *(uint4*)(hi + 16) = make_uint4(h[4], h[5], h[6], h[7]);
    *(uint4*)(lo)      = make_uint4(l[0], l[1], l[2], l[3]);
    *(uint4*)(lo + 16) = make_uint4(l[4], l[5], l[6], l[7]);
}

__global__ void __launch_bounds__(256) mgemm_nt(const float* __restrict__ A,
                                                const float* __restrict__ W,
                                                float* __restrict__ C,
                                                int M, int N, int K) {
    extern __shared__ char sm[];
    const uint32_t sbase = smem_u32(sm);

    const int tid = threadIdx.x;
    const int wid = tid >> 5, lane = tid & 31;
    const int m0 = blockIdx.y * 128, n0 = blockIdx.x * 128;
    const int wm = wid & 1, wn = wid >> 1;       // warp tile: rows wm*64, cols wn*32

    const int lrow = tid >> 1;
    const int lkh  = (tid & 1) * 16;
    const float* aptr = A + (size_t)(m0 + lrow) * K + lkh;
    const float* bptr = W + (size_t)(n0 + lrow) * K + lkh;
    const int stsoff = lrow * 80 + lkh * 2;

    float acc[4][4][4];
#pragma unroll
    for (int i = 0; i < 4; ++i)
#pragma unroll
        for (int j = 0; j < 4; ++j)
#pragma unroll
            for (int q = 0; q < 4; ++q) acc[i][j][q] = 0.f;

    const int nchunk = K >> 5;

    {
        float4 av[4], bv[4];
#pragma unroll
        for (int j = 0; j < 4; ++j) { av[j] = *(const float4*)(aptr + j * 4); bv[j] = *(const float4*)(bptr + j * 4); }
        sts_split(sm + 0 * MG_TILE + stsoff, sm + 1 * MG_TILE + stsoff, av);
        sts_split(sm + 2 * MG_TILE + stsoff, sm + 3 * MG_TILE + stsoff, bv);
    }
    __syncthreads();

    for (int c = 0; c < nchunk; ++c) {
        const int p = c & 1;
        const uint32_t buf = sbase + p * MG_STAGE;

        float4 av[4], bv[4];
        if (c + 1 < nchunk) {
            const float* ap = aptr + (c + 1) * 32;
            const float* bp = bptr + (c + 1) * 32;
#pragma unroll
            for (int j = 0; j < 4; ++j) { av[j] = *(const float4*)(ap + j * 4); bv[j] = *(const float4*)(bp + j * 4); }
        }

#pragma unroll
        for (int ks = 0; ks < 2; ++ks) {
            const int kk = ks * 16;
            uint32_t bh[4][2], bl[4][2];
#pragma unroll
            for (int half = 0; half < 2; ++half) {
                const int n = wn * 32 + half * 16;
                const uint32_t rowb = (uint32_t)(n + (lane & 7) + ((lane & 16) >> 1));
                const uint32_t colb = (uint32_t)(kk + (lane & 8));
                const uint32_t addr = buf + 2 * MG_TILE + rowb * 80 + colb * 2;
                uint32_t r[4];
                ldm_x4(r, addr);
                bh[half * 2][0] = r[0]; bh[half * 2][1] = r[1];
                bh[half * 2 + 1][0] = r[2]; bh[half * 2 + 1][1] = r[3];
                ldm_x4(r, addr + MG_TILE);
                bl[half * 2][0] = r[0]; bl[half * 2][1] = r[1];
                bl[half * 2 + 1][0] = r[2]; bl[half * 2 + 1][1] = r[3];
            }
#pragma unroll
            for (int mf = 0; mf < 4; ++mf) {
                const int m = wm * 64 + mf * 16;
                const uint32_t rowa = (uint32_t)(m + (lane & 15));
                const uint32_t cola = (uint32_t)(kk + ((lane >> 4) << 3));
                const uint32_t addr = buf + rowa * 80 + cola * 2;
                uint32_t ah[4], al[4];
                ldm_x4(ah, addr);
                ldm_x4(al, addr + MG_TILE);
#pragma unroll
                for (int nf = 0; nf < 4; ++nf) {
                    mma_bf16(acc[mf][nf], ah, bh[nf]);
                    mma_bf16(acc[mf][nf], ah, bl[nf]);
                    mma_bf16(acc[mf][nf], al, bh[nf]);
                }
            }
        }

        if (c + 1 < nchunk) {
            char* nb = sm + (p ^ 1) * MG_STAGE;
            sts_split(nb + 0 * MG_TILE + stsoff, nb + 1 * MG_TILE + stsoff, av);
            sts_split(nb + 2 * MG_TILE + stsoff, nb + 3 * MG_TILE + stsoff, bv);
            __syncthreads();
        }
    }

#pragma unroll
    for (int mf = 0; mf < 4; ++mf) {
        const int row = m0 + wm * 64 + mf * 16 + (lane >> 2);
#pragma unroll
        for (int nf = 0; nf < 4; ++nf) {
            const int col = n0 + wn * 32 + nf * 8 + (lane & 3) * 2;
            *(float2*)(C + (size_t)row * N + col)       = make_float2(acc[mf][nf][0], acc[mf][nf][1]);
            *(float2*)(C + (size_t)(row + 8) * N + col) = make_float2(acc[mf][nf][2], acc[mf][nf][3]);
        }
    }
}

// ---------------- RoPE on q (16 heads) and k (8 heads), in place ----------------
__global__ void rope_kernel(const float* __restrict__ cosp,
                            const float* __restrict__ sinp) {
    int idx = blockIdx.x * blockDim.x + threadIdx.x;  // < B*S*24*32
    int d  = idx & 31;
    int t  = idx >> 5;
    int hh = t % 24;
    int t2 = t / 24;
    int s  = t2 % CS;
    int b  = t2 / CS;

    const float* cb = cosp + ((size_t)b * CS + s) * CHD;
    const float* sb = sinp + ((size_t)b * CS + s) * CHD;
    float c1 = cb[d],      s1 = sb[d];
    float c2 = cb[d + 32], s2 = sb[d + 32];

    float* base;
    if (hh < CH) base = g_q + ((size_t)b * CS + s) * CQN + hh * CHD;
    else         base = g_k + ((size_t)b * CS + s) * CKN + (hh - CH) * CHD;

    float x1 = base[d];
    float x2 = base[d + 32];
    base[d]      = x1 * c1 - x2 * s1;
    base[d + 32] = x2 * c2 + x1 * s2;
}

// ---------------- dt -> dyn = exp(A[h] * softplus(dt)) ----------------
__global__ void __launch_bounds__(256) dt_kernel(const float* __restrict__ Wdt,
                                                 const float* __restrict__ Avec) {
    __shared__ float vsh[CKN];
    int bs = blockIdx.x;               // b*S + s
    int b = bs / CS, s = bs % CS;
    int tid = threadIdx.x;
    vsh[tid]        = g_v[(size_t)bs * CKN + tid];
    vsh[tid + 256]  = g_v[(size_t)bs * CKN + tid + 256];
    __syncthreads();

    int warp = tid >> 5, lane = tid & 31;
    for (int h = warp; h < CH; h += 8) {
        const float* wrow = Wdt + (size_t)h * CKN;
        float acc = 0.f;
        for (int j = lane; j < CKN; j += 32) acc = fmaf(vsh[j], wrow[j], acc);
#pragma unroll
        for (int off = 16; off > 0; off >>= 1)
            acc += __shfl_down_sync(0xffffffffu, acc, off);
        if (lane == 0) {
            float x = acc;
            float sp = fmaxf(x, 0.f) + log1pf(expf(-fabsf(x)));   // softplus
            g_dyn[((size_t)b * CH + h) * CS + s] = expf(Avec[h] * sp);
        }
    }
}

// ---------------- per-(b,h): sort 2048 dyn values, threshold, first-unmasked ----------------
__global__ void __launch_bounds__(256) rate_kernel() {
    __shared__ float sv[CS];
    __shared__ float s_rate;
    __shared__ int   s_fu;
    int bh = blockIdx.x;
    int tid = threadIdx.x;
    float* dptr = g_dyn + (size_t)bh * CS;

    for (int i = tid; i < CS; i += 256) sv[i] = dptr[i];
    __syncthreads();

    for (int k = 2; k <= CS; k <<= 1) {
        for (int j = k >> 1; j > 0; j >>= 1) {
            for (int i = tid; i < CS; i += 256) {
                int ixj = i ^ j;
                if (ixj > i) {
                    float a = sv[i], c = sv[ixj];
                    bool up = ((i & k) == 0);
                    if (up ? (a > c) : (a < c)) { sv[i] = c; sv[ixj] = a; }
                }
            }
            __syncthreads();
        }
    }
    if (tid == 0) { s_rate = sv[KTH_IDX]; s_fu = CS; }
    __syncthreads();

    float rate = s_rate;
    for (int i = tid; i < CS; i += 256) {
        float m = dptr[i];
        if (m < rate) dptr[i] = -FLT_MAX;
        else          atomicMin(&s_fu, i);
    }
    __syncthreads();
    if (tid == 0) g_fu[bh] = s_fu;
}

// ---------------- tensor-core causal flash attention (64 q-rows/block, bf16x3) ----------------
// 128 threads = 4 warps; warp w owns q-rows [w*16, w*16+16).
// smem pitch 72 halves (144B): 9*r mod 8 distinct -> conflict-free ldmatrix.
struct alignas(16) AttnSmem2 {
    uint16_t KsH[64 * 72];   // K tile hi (also Q staging)    offset 0
    uint16_t KsL[64 * 72];   // K tile lo                     offset 9216
    uint16_t VsH[64 * 72];   // V^T tile hi ([d][key])        offset 18432
    uint16_t VsL[64 * 72];   // V^T tile lo                   offset 27648
    float    mb[64];         // dyn mask bias                 offset 36864
};

__global__ void __launch_bounds__(128) attn_mma_kernel() {
    __shared__ AttnSmem2 sm;
    const int tid = threadIdx.x, lane = tid & 31, w = tid >> 5;
    const int qt = blockIdx.x, bh = blockIdx.y;
    const int b = bh >> 4, h = bh & 15, kvh = h >> 1;
    const uint32_t ksh = smem_u32(sm.KsH);
    const uint32_t vsh = smem_u32(sm.VsH);

    const int lrow = tid >> 1;               // staging: row 0..63
    const int lcol = (tid & 1) * 32;         // staging: col half

    // ---- stage Q tile (64 x 64 f32) into KsH/KsL as bf16 hi/lo ----
    {
        const float* qp = g_q + ((size_t)(b * CS + qt * 64 + lrow)) * CQN + h * CHD + lcol;
        uint16_t* dh = sm.KsH + lrow * 72 + lcol;
        uint16_t* dl = sm.KsL + lrow * 72 + lcol;
#pragma unroll
        for (int j = 0; j < 8; ++j) {
            float4 v = *(const float4*)(qp + j * 4);
            uint32_t h0 = bf2(v.x, v.y), h1 = bf2(v.z, v.w);
            uint32_t l0 = bf2(v.x - hif_lo(h0), v.y - hif_hi(h0));
            uint32_t l1 = bf2(v.z - hif_lo(h1), v.w - hif_hi(h1));
            *(uint2*)(dh + j * 4) = make_uint2(h0, h1);
            *(uint2*)(dl + j * 4) = make_uint2(l0, l1);
        }
    }
    __syncthreads();

    // ---- Q fragments (held in registers for the whole kernel) ----
    uint32_t qhf[4][4], qlf[4][4];
    {
        const uint32_t rowa = (uint32_t)(w * 16 + (lane & 15));
        const uint32_t cola0 = (uint32_t)((lane >> 4) << 3);
#pragma unroll
        for (int ks = 0; ks < 4; ++ks) {
            uint32_t addr = ksh + rowa * 144 + (ks * 16 + cola0) * 2;
            ldm_x4(qhf[ks], addr);
            ldm_x4(qlf[ks], addr + 9216);
        }
    }
    __syncthreads();

    float oacc[8][4];
#pragma unroll
    for (int nf = 0; nf < 8; ++nf)
#pragma unroll
        for (int j = 0; j < 4; ++j) oacc[nf][j] = 0.f;

    float mrun0 = -1e30f, mrun1 = -1e30f, lrun0 = 0.f, lrun1 = 0.f;
    const int row0 = lane >> 2;              // tile-local rows: w*16+row0, +8
    const int qi0 = w * 16 + row0, qi1 = qi0 + 8;

    for (int kt = 0; kt <= qt; ++kt) {
        // ---- stage K tile ----
        {
            const float* kp = g_k + ((size_t)(b * CS + kt * 64 + lrow)) * CKN + kvh * CHD + lcol;
            uint16_t* dh = sm.KsH + lrow * 72 + lcol;
            uint16_t* dl = sm.KsL + lrow * 72 + lcol;
#pragma unroll
            for (int j = 0; j < 8; ++j) {
                float4 v = *(const float4*)(kp + j * 4);
                uint32_t h0 = bf2(v.x, v.y), h1 = bf2(v.z, v.w);
                uint32_t l0 = bf2(v.x - hif_lo(h0), v.y - hif_hi(h0));
                uint32_t l1 = bf2(v.z - hif_lo(h1), v.w - hif_hi(h1));
                *(uint2*)(dh + j * 4) = make_uint2(h0, h1);
                *(uint2*)(dl + j * 4) = make_uint2(l0, l1);
            }
        }
        // ---- stage V tile transposed: Vs[d][key] ----
        {
            const int key = tid & 63, dblk = (tid >> 6) * 32;
            const float* vp = g_v + ((size_t)(b * CS + kt * 64 + key)) * CKN + kvh * CHD + dblk;
#pragma unroll
            for (int j = 0; j < 8; ++j) {
                float4 v = *(const float4*)(vp + j * 4);
                float vv[4] = {v.x, v.y, v.z, v.w};
                const int d0 = dblk + j * 4;
#pragma unroll
                for (int e = 0; e < 4; ++e) {
                    uint32_t hp = bf2(vv[e], 0.f);
                    uint32_t lp = bf2(vv[e] - hif_lo(hp), 0.f);
                    sm.VsH[(d0 + e) * 72 + key] = (uint16_t)(hp & 0xFFFFu);
                    sm.VsL[(d0 + e) * 72 + key] = (uint16_t)(lp & 0xFFFFu);
                }
            }
        }
        if (tid < 64) sm.mb[tid] = g_dyn[(size_t)bh * CS + kt * 64 + tid];
        __syncthreads();

        // ---- S = Q @ K^T (m16 x n64 per warp, bf16x3) ----
        float sc[8][4];
#pragma unroll
        for (int nf = 0; nf < 8; ++nf)
#pragma unroll
            for (int j = 0; j < 4; ++j) sc[nf][j] = 0.f;

#pragma unroll
        for (int ks = 0; ks < 4; ++ks) {
#pragma unroll
            for (int g = 0; g < 4; ++g) {
                const uint32_t rowb = (uint32_t)(g * 16 + (lane & 7) + ((lane & 16) >> 1));
                const uint32_t colb = (uint32_t)(ks * 16 + (lane & 8));
                const uint32_t addr = ksh + rowb * 144 + colb * 2;
                uint32_t kh[4], kl[4];
                ldm_x4(kh, addr);
                ldm_x4(kl, addr + 9216);
                mma_bf16(sc[2 * g],     qhf[ks], kh);
                mma_bf16(sc[2 * g],     qhf[ks], kl);
                mma_bf16(sc[2 * g],     qlf[ks], kh);
                mma_bf16(sc[2 * g + 1], qhf[ks], kh + 2);
                mma_bf16(sc[2 * g + 1], qhf[ks], kl + 2);
                mma_bf16(sc[2 * g + 1], qlf[ks], kh + 2);
            }
        }

        // ---- online softmax (rows owned by 4-lane groups) ----
        const bool diag = (kt == qt);
        float mx0 = -1e30f, mx1 = -1e30f;
#pragma unroll
        for (int nf = 0; nf < 8; ++nf) {
            const int c0 = nf * 8 + (lane & 3) * 2;
            const float b0 = sm.mb[c0], b1 = sm.mb[c0 + 1];
            float s00 = sc[nf][0] * CSCALE + b0;
            float s01 = sc[nf][1] * CSCALE + b1;
            float s10 = sc[nf][2] * CSCALE + b0;
            float s11 = sc[nf][3] * CSCALE + b1;
            if (diag) {
                if (c0 > qi0)     s00 = -FLT_MAX;
                if (c0 + 1 > qi0) s01 = -FLT_MAX;
                if (c0 > qi1)     s10 = -FLT_MAX;
                if (c0 + 1 > qi1) s11 = -FLT_MAX;
            }
            sc[nf][0] = s00; sc[nf][1] = s01; sc[nf][2] = s10; sc[nf][3] = s11;
            mx0 = fmaxf(mx0, fmaxf(s00, s01));
            mx1 = fmaxf(mx1, fmaxf(s10, s11));
        }
        mx0 = fmaxf(mx0, __shfl_xor_sync(0xffffffffu, mx0, 1));
        mx0 = fmaxf(mx0, __shfl_xor_sync(0xffffffffu, mx0, 2));
        mx1 = fmaxf(mx1, __shfl_xor_sync(0xffffffffu, mx1, 1));
        mx1 = fmaxf(mx1, __shfl_xor_sync(0xffffffffu, mx1, 2));

        const float mn0 = fmaxf(mrun0, mx0), mn1 = fmaxf(mrun1, mx1);
        const float esc0 = __expf(mrun0 - mn0), esc1 = __expf(mrun1 - mn1);
        mrun0 = mn0; mrun1 = mn1;

        float sum0 = 0.f, sum1 = 0.f;
#pragma unroll
        for (int nf = 0; nf < 8; ++nf) {
            float p00 = __expf(sc[nf][0] - mn0);
            float p01 = __expf(sc[nf][1] - mn0);
            float p10 = __expf(sc[nf][2] - mn1);
            float p11 = __expf(sc[nf][3] - mn1);
            sc[nf][0] = p00; sc[nf][1] = p01; sc[nf][2] = p10; sc[nf][3] = p11;
            sum0 += p00 + p01;
            sum1 += p10 + p11;
        }
        sum0 += __shfl_xor_sync(0xffffffffu, sum0, 1);
        sum0 += __shfl_xor_sync(0xffffffffu, sum0, 2);
        sum1 += __shfl_xor_sync(0xffffffffu, sum1, 1);
        sum1 += __shfl_xor_sync(0xffffffffu, sum1, 2);
        lrun0 = lrun0 * esc0 + sum0;
        lrun1 = lrun1 * esc1 + sum1;

#pragma unroll
        for (int nf = 0; nf < 8; ++nf) {
            oacc[nf][0] *= esc0; oacc[nf][1] *= esc0;
            oacc[nf][2] *= esc1; oacc[nf][3] *= esc1;
        }

        // ---- O += P @ V  (P from sc regs, bf16x3) ----
#pragma unroll
        for (int ks = 0; ks < 4; ++ks) {
            uint32_t ah[4], al[4];
            ah[0] = bf2(sc[2 * ks][0], sc[2 * ks][1]);
            ah[1] = bf2(sc[2 * ks][2], sc[2 * ks][3]);
            ah[2] = bf2(sc[2 * ks + 1][0], sc[2 * ks + 1][1]);
            ah[3] = bf2(sc[2 * ks + 1][2], sc[2 * ks + 1][3]);
            al[0] = bf2(sc[2 * ks][0] - hif_lo(ah[0]), sc[2 * ks][1] - hif_hi(ah[0]));
            al[1] = bf2(sc[2 * ks][2] - hif_lo(ah[1]), sc[2 * ks][3] - hif_hi(ah[1]));
            al[2] = bf2(sc[2 * ks + 1][0] - hif_lo(ah[2]), sc[2 * ks + 1][1] - hif_hi(ah[2]));
            al[3] = bf2(sc[2 * ks + 1][2] - hif_lo(ah[3]), sc[2 * ks + 1][3] - hif_hi(ah[3]));
#pragma unroll
            for (int g = 0; g < 4; ++g) {
                const uint32_t rowb = (uint32_t)(g * 16 + (lane & 7) + ((lane & 16) >> 1));
                const uint32_t colb = (uint32_t)(ks * 16 + (lane & 8));
                const uint32_t addr = vsh + rowb * 144 + colb * 2;
                uint32_t vh4[4], vl4[4];
                ldm_x4(vh4, addr);
                ldm_x4(vl4, addr + 9216);
                mma_bf16(oacc[2 * g],     ah, vh4);
                mma_bf16(oacc[2 * g],     ah, vl4);
                mma_bf16(oacc[2 * g],     al, vh4);
                mma_bf16(oacc[2 * g + 1], ah, vh4 + 2);
                mma_bf16(oacc[2 * g + 1], ah, vl4 + 2);
                mma_bf16(oacc[2 * g + 1], al, vh4 + 2);
            }
        }
        __syncthreads();
    }

    // ---- epilogue ----
    const float inv0 = 1.f / lrun0, inv1 = 1.f / lrun1;
    const int grow0 = qt * 64 + w * 16 + row0;
    float* ob0 = g_attn + ((size_t)(b * CS + grow0)) * CQN + h * CHD;
    float* ob1 = g_attn + ((size_t)(b * CS + grow0 + 8)) * CQN + h * CHD;
#pragma unroll
    for (int nf = 0; nf < 8; ++nf) {
        const int col = nf * 8 + (lane & 3) * 2;
        *(float2*)(ob0 + col) = make_float2(oacc[nf][0] * inv0, oacc[nf][1] * inv0);
        *(float2*)(ob1 + col) = make_float2(oacc[nf][2] * inv1, oacc[nf][3] * inv1);
    }
}

// ---------------- exact full-row fixup for rows with fully-masked causal prefix ----------------
__global__ void __launch_bounds__(256) fixup_kernel() {
    __shared__ float qrow[CHD];
    __shared__ float s_sh[CS];
    __shared__ float red[256];
    __shared__ float s_max, s_den;

    int bh = blockIdx.x;
    int b = bh >> 4, h = bh & 15, kvh = h >> 1;
    int tid = threadIdx.x;
    int fu = g_fu[bh];
    if (fu <= 0) return;

    for (int qi = 0; qi < fu; ++qi) {
        if (tid < CHD) qrow[tid] = g_q[((size_t)(b * CS + qi)) * CQN + h * CHD + tid];
        __syncthreads();

        float lm = -FLT_MAX;
        for (int ki = tid; ki < CS; ki += 256) {
            const float* krow = g_k + ((size_t)(b * CS + ki)) * CKN + kvh * CHD;
            float dot = 0.f;
#pragma unroll 16
            for (int d = 0; d < CHD; ++d) dot = fmaf(qrow[d], krow[d], dot);
            float mv = g_dyn[(size_t)bh * CS + ki] + ((ki <= qi) ? 0.0f : CNEG);
            float sc = dot * CSCALE + mv;
            s_sh[ki] = sc;
            lm = fmaxf(lm, sc);
        }
        red[tid] = lm;
        __syncthreads();
        for (int off = 128; off > 0; off >>= 1) {
            if (tid < off) red[tid] = fmaxf(red[tid], red[tid + off]);
            __syncthreads();
        }
        if (tid == 0) s_max = red[0];
        __syncthreads();

        float ls = 0.f;
        float rmax = s_max;
        for (int ki = tid; ki < CS; ki += 256) {
            float w = expf(s_sh[ki] - rmax);
            s_sh[ki] = w;
            ls += w;
        }
        red[tid] = ls;
        __syncthreads();
        for (int off = 128; off > 0; off >>= 1) {
            if (tid < off) red[tid] += red[tid + off];
            __syncthreads();
        }
        if (tid == 0) s_den = red[0];
        __syncthreads();

        int d = tid & 63, part = tid >> 6;
        float oacc = 0.f;
        for (int ki = part; ki < CS; ki += 4)
            oacc = fmaf(s_sh[ki], g_v[((size_t)(b * CS + ki)) * CKN + kvh * CHD + d], oacc);
        red[tid] = oacc;
        __syncthreads();
        if (tid < 64) {
            float tot = red[tid] + red[tid + 64] + red[tid + 128] + red[tid + 192];
            g_attn[((size_t)(b * CS + qi)) * CQN + h * CHD + d] = tot / s_den;
        }
        __syncthreads();
    }
}

// ---------------- host launcher ----------------
static void launch_mgemm(const float* A, const float* W, float* C, int M, int N, int K) {
    cudaFuncSetAttribute(mgemm_nt, cudaFuncAttributeMaxDynamicSharedMemorySize, MG_SMEM);
    mgemm_nt<<<dim3(N / 128, M / 128), 256, MG_SMEM>>>(A, W, C, M, N, K);
}

extern "C" void kernel_launch(void* const* d_in, const int* in_sizes, int n_in,
                              void* d_out, int out_size) {
    const float* hs   = (const float*)d_in[0];
    const float* cosp = (const float*)d_in[1];
    const float* sinp = (const float*)d_in[2];
    const float* Wq   = (const float*)d_in[4];
    const float* Wk   = (const float*)d_in[5];
    const float* Wv   = (const float*)d_in[6];
    const float* Avec = (const float*)d_in[7];
    const float* Wdt  = (const float*)d_in[8];
    const float* Wo   = (const float*)d_in[9];
    float* out = (float*)d_out;

    float *pq, *pk, *pv, *pattn;
    cudaGetSymbolAddress((void**)&pq, g_q);
    cudaGetSymbolAddress((void**)&pk, g_k);
    cudaGetSymbolAddress((void**)&pv, g_v);
    cudaGetSymbolAddress((void**)&pattn, g_attn);

    const int M = CB * CS;  // 4096

    // projections on HMMA (bf16x3 via mma.sync)
    launch_mgemm(hs, Wq, pq, M, CQN, CHID);
    launch_mgemm(hs, Wk, pk, M, CKN, CHID);
    launch_mgemm(hs, Wv, pv, M, CKN, CHID);

    // rope on q,k
    rope_kernel<<<(CB * CS * (CH + CKVH) * 32) / 256, 256>>>(cosp, sinp);

    // dyn mask pipeline
    dt_kernel<<<M, 256>>>(Wdt, Avec);
    rate_kernel<<<CB * CH, 256>>>();

    // attention on HMMA
    attn_mma_kernel<<<dim3(CS / 64, CB * CH), 128>>>();
    fixup_kernel<<<CB * CH, 256>>>();

    // output projection
    launch_mgemm(pattn, Wo, out, M, CHID, CQN);
}